// round 1
// baseline (speedup 1.0000x reference)
#include <cuda_runtime.h>
#include <math.h>

#define B_   2
#define T_   2048
#define HID  1024
#define NH   16
#define HD   64

// ---------------- scratch (device globals; no allocations allowed) ----------
__device__ float g_qkv[B_ * T_ * 3 * HID];          // [B*T, 3072]
__device__ float g_Q[B_ * NH * T_ * HD];            // [B,H,T,D]
__device__ float g_K[B_ * NH * T_ * HD];
__device__ float g_V[B_ * NH * T_ * HD];
__device__ float g_att[B_ * T_ * HID];              // [B*T, 1024] (already (b,t,h*64+d))
__device__ signed char g_gmask[B_ * T_];
__device__ int g_gcnt[B_];
__device__ int g_glist[B_ * T_];

// ---------------- SGEMM: C[M,N] = A[M,K] * W[N,K]^T + bias[N] ---------------
// 128x128 tile, BK=8, 256 threads, 8x8 per-thread microtile.
__global__ __launch_bounds__(256) void sgemm_nt(
    const float* __restrict__ A, const float* __restrict__ W,
    const float* __restrict__ bias, float* __restrict__ C,
    int M, int N, int K)
{
    __shared__ float As[8][128];
    __shared__ float Bs[8][128];

    const int tid = threadIdx.x;
    const int tx  = tid & 15;      // N dir
    const int ty  = tid >> 4;      // M dir
    const float* Ab = A + (size_t)blockIdx.y * 128 * K;
    const float* Wb = W + (size_t)blockIdx.x * 128 * K;

    const int lrow = tid >> 1;
    const int lcol = (tid & 1) * 4;

    float acc[8][8];
    #pragma unroll
    for (int i = 0; i < 8; i++)
        #pragma unroll
        for (int j = 0; j < 8; j++) acc[i][j] = 0.f;

    for (int k0 = 0; k0 < K; k0 += 8) {
        float4 av = *(const float4*)(Ab + (size_t)lrow * K + k0 + lcol);
        float4 wv = *(const float4*)(Wb + (size_t)lrow * K + k0 + lcol);
        As[lcol + 0][lrow] = av.x; As[lcol + 1][lrow] = av.y;
        As[lcol + 2][lrow] = av.z; As[lcol + 3][lrow] = av.w;
        Bs[lcol + 0][lrow] = wv.x; Bs[lcol + 1][lrow] = wv.y;
        Bs[lcol + 2][lrow] = wv.z; Bs[lcol + 3][lrow] = wv.w;
        __syncthreads();

        #pragma unroll
        for (int kk = 0; kk < 8; kk++) {
            float a[8], b[8];
            *(float4*)&a[0] = *(const float4*)&As[kk][ty * 8];
            *(float4*)&a[4] = *(const float4*)&As[kk][ty * 8 + 4];
            *(float4*)&b[0] = *(const float4*)&Bs[kk][tx * 8];
            *(float4*)&b[4] = *(const float4*)&Bs[kk][tx * 8 + 4];
            #pragma unroll
            for (int i = 0; i < 8; i++)
                #pragma unroll
                for (int j = 0; j < 8; j++)
                    acc[i][j] = fmaf(a[i], b[j], acc[i][j]);
        }
        __syncthreads();
    }

    const int row0 = blockIdx.y * 128 + ty * 8;
    const int col0 = blockIdx.x * 128 + tx * 8;
    #pragma unroll
    for (int i = 0; i < 8; i++) {
        #pragma unroll
        for (int j = 0; j < 8; j += 4) {
            float4 v;
            v.x = acc[i][j + 0] + bias[col0 + j + 0];
            v.y = acc[i][j + 1] + bias[col0 + j + 1];
            v.z = acc[i][j + 2] + bias[col0 + j + 2];
            v.w = acc[i][j + 3] + bias[col0 + j + 3];
            *(float4*)(C + (size_t)(row0 + i) * N + col0 + j) = v;
        }
    }
}

// ---------------- RoPE + split qkv -> Q,K,V [B,H,T,D] -----------------------
// ROPE_DIM == HEAD_DIM == 64, so the entire head rotates; half = 32.
__global__ void rope_kernel()
{
    int idx = blockIdx.x * blockDim.x + threadIdx.x;   // B*T*NH*32 = 2^21 threads
    int i = idx & 31;
    int h = (idx >> 5) & (NH - 1);
    int t = (idx >> 9) & (T_ - 1);
    int b = idx >> 20;

    const float* base = g_qkv + (size_t)(b * T_ + t) * (3 * HID);

    // inv_freq = 10000^(-i/32), computed in double then rounded to fp32
    // (matches reference fp32 power to ~1 ulp); angle formed in fp32 like ref.
    float invf = (float)exp((double)i * (-log(10000.0) / 32.0));
    float ang = (float)t * invf;
    float s, c;
    sincosf(ang, &s, &c);

    int col = h * HD + i;
    float q1 = base[col],           q2 = base[col + 32];
    float k1 = base[HID + col],     k2 = base[HID + col + 32];
    float v1 = base[2 * HID + col], v2 = base[2 * HID + col + 32];

    size_t o = (((size_t)b * NH + h) * T_ + t) * HD + i;
    g_Q[o]      = q1 * c - q2 * s;
    g_Q[o + 32] = q1 * s + q2 * c;
    g_K[o]      = k1 * c - k2 * s;
    g_K[o + 32] = k1 * s + k2 * c;
    g_V[o]      = v1;
    g_V[o + 32] = v2;
}

// ---------------- global-token mask + list ----------------------------------
__global__ void ginit_kernel()
{
    if (threadIdx.x < B_) g_gcnt[threadIdx.x] = 0;
}

__global__ void gmask_kernel(const int* __restrict__ ids)
{
    int idx = blockIdx.x * blockDim.x + threadIdx.x;
    if (idx >= B_ * T_) return;
    int id = ids[idx];
    // global_idx is deterministically [0,1,2] from setup_inputs
    bool g = (id >= 0 && id <= 2);
    g_gmask[idx] = g ? 1 : 0;
    if (g) {
        int b = idx / T_;
        int p = atomicAdd(&g_gcnt[b], 1);
        g_glist[b * T_ + p] = idx - b * T_;
    }
}

// ---------------- flash attention (causal + global columns) -----------------
// 1 block = 128 q rows of one (b,h). 1 thread = 1 q row.
// Q row + O accumulator in registers; K/V tiles (32 keys) in SMEM (broadcast).
// Causal tiles cover k < q0+128; rare global tokens beyond handled in a tail.
__global__ __launch_bounds__(128) void attn_kernel()
{
    const int b  = blockIdx.z;
    const int h  = blockIdx.y;
    const int q0 = blockIdx.x * 128;
    const int tid = threadIdx.x;
    const int q = q0 + tid;

    const size_t head_off = ((size_t)b * NH + h) * T_ * HD;
    const float* Qr = g_Q + head_off + (size_t)q * HD;
    const float* Kb = g_K + head_off;
    const float* Vb = g_V + head_off;

    float qreg[HD];
    #pragma unroll
    for (int d = 0; d < HD; d += 4) {
        float4 v = *(const float4*)(Qr + d);
        qreg[d] = v.x; qreg[d + 1] = v.y; qreg[d + 2] = v.z; qreg[d + 3] = v.w;
    }
    float oacc[HD];
    #pragma unroll
    for (int d = 0; d < HD; d++) oacc[d] = 0.f;
    float m = -1e30f, l = 0.f;

    __shared__ float Ks[32][HD];
    __shared__ float Vs[32][HD];
    __shared__ signed char gm[32];

    const int kend = q0 + 128;   // last causal tile end (multiple of 32)

    for (int t0 = 0; t0 < kend; t0 += 32) {
        #pragma unroll 4
        for (int i = tid; i < 32 * 16; i += 128) {
            int r = i >> 4, c = (i & 15) << 2;
            *(float4*)&Ks[r][c] = *(const float4*)(Kb + (size_t)(t0 + r) * HD + c);
            *(float4*)&Vs[r][c] = *(const float4*)(Vb + (size_t)(t0 + r) * HD + c);
        }
        if (tid < 32) gm[tid] = g_gmask[b * T_ + t0 + tid];
        __syncthreads();

        #pragma unroll
        for (int ch = 0; ch < 2; ch++) {
            float s[16];
            #pragma unroll
            for (int jj = 0; jj < 16; jj++) {
                const int j = ch * 16 + jj;
                float acc = 0.f;
                #pragma unroll
                for (int d = 0; d < HD; d++)
                    acc = fmaf(qreg[d], Ks[j][d], acc);
                int k = t0 + j;
                bool allow = (k <= q) || (gm[j] != 0);
                s[jj] = allow ? acc * 0.125f : -1e30f;
            }
            float cmax = s[0];
            #pragma unroll
            for (int jj = 1; jj < 16; jj++) cmax = fmaxf(cmax, s[jj]);
            float mnew = fmaxf(m, cmax);
            float alpha = __expf(m - mnew);
            l *= alpha;
            #pragma unroll
            for (int d = 0; d < HD; d++) oacc[d] *= alpha;
            #pragma unroll
            for (int jj = 0; jj < 16; jj++) {
                const int j = ch * 16 + jj;
                float p = __expf(s[jj] - mnew);
                l += p;
                #pragma unroll
                for (int d = 0; d < HD; d++)
                    oacc[d] = fmaf(p, Vs[j][d], oacc[d]);
            }
            m = mnew;
        }
        __syncthreads();
    }

    // Tail: global tokens with k >= kend (expected O(1) per batch; id in [0,2]
    // occurs ~3/32000 of the time). All rows attend to these columns.
    const int ng = g_gcnt[b];
    for (int gi = 0; gi < ng; gi++) {
        int k = g_glist[b * T_ + gi];
        if (k < kend) continue;   // already handled via gm in the tile loop
        const float* Kr = Kb + (size_t)k * HD;
        const float* Vr = Vb + (size_t)k * HD;
        float acc = 0.f;
        #pragma unroll
        for (int d = 0; d < HD; d++) acc = fmaf(qreg[d], __ldg(Kr + d), acc);
        float sv = acc * 0.125f;
        float mnew = fmaxf(m, sv);
        float alpha = __expf(m - mnew);
        float p = __expf(sv - mnew);
        l = l * alpha + p;
        #pragma unroll
        for (int d = 0; d < HD; d++)
            oacc[d] = oacc[d] * alpha + p * __ldg(Vr + d);
        m = mnew;
    }

    float inv = 1.f / l;
    float* Or = g_att + ((size_t)(b * T_ + q)) * HID + h * HD;
    #pragma unroll
    for (int d = 0; d < HD; d += 4) {
        float4 v;
        v.x = oacc[d + 0] * inv; v.y = oacc[d + 1] * inv;
        v.z = oacc[d + 2] * inv; v.w = oacc[d + 3] * inv;
        *(float4*)(Or + d) = v;
    }
}

// ---------------- launch -----------------------------------------------------
extern "C" void kernel_launch(void* const* d_in, const int* in_sizes, int n_in,
                              void* d_out, int out_size)
{
    (void)in_sizes; (void)n_in; (void)out_size;
    const float* x      = (const float*)d_in[0];
    const int*   ids    = (const int*)d_in[1];
    const float* qkv_w  = (const float*)d_in[2];
    const float* qkv_b  = (const float*)d_in[3];
    const float* out_w  = (const float*)d_in[4];
    const float* out_b  = (const float*)d_in[5];
    float*       out    = (float*)d_out;

    float *p_qkv = nullptr, *p_att = nullptr;
    cudaGetSymbolAddress((void**)&p_qkv, g_qkv);
    cudaGetSymbolAddress((void**)&p_att, g_att);

    // 1. qkv = x @ qkv_w^T + qkv_b      [4096, 3072]
    sgemm_nt<<<dim3(3 * HID / 128, (B_ * T_) / 128), 256>>>(
        x, qkv_w, qkv_b, p_qkv, B_ * T_, 3 * HID, HID);

    // 2. RoPE + split to [B,H,T,D]
    rope_kernel<<<(B_ * T_ * NH * 32) / 256, 256>>>();

    // 3. global-token mask + list
    ginit_kernel<<<1, 32>>>();
    gmask_kernel<<<(B_ * T_ + 255) / 256, 256>>>(ids);

    // 4. attention -> g_att [B*T, 1024]
    attn_kernel<<<dim3(T_ / 128, NH, B_), 128>>>();

    // 5. out = att @ out_w^T + out_b   [4096, 1024]
    sgemm_nt<<<dim3(HID / 128, (B_ * T_) / 128), 256>>>(
        p_att, out_w, out_b, out, B_ * T_, HID, HID);
}

// round 3
// speedup vs baseline: 1.3230x; 1.3230x over previous
#include <cuda_runtime.h>
#include <math.h>
#include <stdint.h>

#define B_   2
#define T_   2048
#define HID  1024
#define NH   16
#define HD   64

// ---------------- scratch (device globals; no allocations allowed) ----------
__device__ float g_qkv[B_ * T_ * 3 * HID];          // [B*T, 3072]
__device__ float g_Q[B_ * NH * T_ * HD];            // [B,H,T,D]
__device__ float g_K[B_ * NH * T_ * HD];
__device__ float g_V[B_ * NH * T_ * HD];
__device__ float g_att[B_ * T_ * HID];              // [B*T, 1024]
__device__ signed char g_gmask[B_ * T_];
__device__ int g_gcnt[B_];
__device__ int g_glist[B_ * T_];

__device__ __forceinline__ uint32_t cvt_tf32(float f) {
    uint32_t r;
    asm("cvt.rna.tf32.f32 %0, %1;" : "=r"(r) : "f"(f));
    return r;
}

// ---------------- TF32 mma.sync GEMM -----------------------------------------
// C[M,N] = A[M,K] @ W[N,K]^T + bias[N].
// CTA tile 128x128, BK=32, 256 threads, warp grid 4(M) x 2(N) -> 32x64/warp.
// Double-buffered SMEM, register prefetch, 1 syncthreads per K-iter.
#define GS_STRIDE 36                       // floats per row (32 + 4 pad)
#define GS_BUF    (128 * GS_STRIDE)        // floats per buffer
#define GS_TOTAL  (4 * GS_BUF * 4)         // bytes: A0,A1,B0,B1

__global__ __launch_bounds__(256) void gemm_tf32_mma(
    const float* __restrict__ A, const float* __restrict__ W,
    const float* __restrict__ bias, float* __restrict__ C,
    int N, int K)
{
    extern __shared__ float sm[];
    float* Asm = sm;                       // 2 buffers
    float* Bsm = sm + 2 * GS_BUF;          // 2 buffers

    const int tid = threadIdx.x;
    const int lane = tid & 31;
    const int wid = tid >> 5;
    const int warp_m = wid & 3;            // 0..3
    const int warp_n = wid >> 2;           // 0..1
    const int row0 = blockIdx.y * 128;
    const int col0 = blockIdx.x * 128;

    const int lrow = tid >> 1;             // 0..127
    const int lseg = (tid & 1) * 16;       // 0 or 16

    const float* Ag = A + (size_t)(row0 + lrow) * K + lseg;
    const float* Bg = W + (size_t)(col0 + lrow) * K + lseg;

    float c[2][8][4];
    #pragma unroll
    for (int mi = 0; mi < 2; mi++)
        #pragma unroll
        for (int ni = 0; ni < 8; ni++)
            #pragma unroll
            for (int r = 0; r < 4; r++) c[mi][ni][r] = 0.f;

    float4 pa[4], pb[4];
    const int nT = K / 32;

    // preload tile 0
    #pragma unroll
    for (int j = 0; j < 4; j++) {
        pa[j] = *(const float4*)(Ag + j * 4);
        pb[j] = *(const float4*)(Bg + j * 4);
    }
    {
        uint32_t* as = (uint32_t*)(Asm) + lrow * GS_STRIDE + lseg;
        uint32_t* bs = (uint32_t*)(Bsm) + lrow * GS_STRIDE + lseg;
        #pragma unroll
        for (int j = 0; j < 4; j++) {
            uint4 ua = { cvt_tf32(pa[j].x), cvt_tf32(pa[j].y),
                         cvt_tf32(pa[j].z), cvt_tf32(pa[j].w) };
            uint4 ub = { cvt_tf32(pb[j].x), cvt_tf32(pb[j].y),
                         cvt_tf32(pb[j].z), cvt_tf32(pb[j].w) };
            *(uint4*)(as + j * 4) = ua;
            *(uint4*)(bs + j * 4) = ub;
        }
    }
    __syncthreads();

    for (int kt = 0; kt < nT; kt++) {
        const int buf = kt & 1;
        // prefetch next tile into registers
        if (kt + 1 < nT) {
            const float* Ap = Ag + (kt + 1) * 32;
            const float* Bp = Bg + (kt + 1) * 32;
            #pragma unroll
            for (int j = 0; j < 4; j++) {
                pa[j] = *(const float4*)(Ap + j * 4);
                pb[j] = *(const float4*)(Bp + j * 4);
            }
        }

        // compute current buffer
        const uint32_t* As_ = (const uint32_t*)(Asm + buf * GS_BUF);
        const uint32_t* Bs_ = (const uint32_t*)(Bsm + buf * GS_BUF);
        #pragma unroll
        for (int ks = 0; ks < 4; ks++) {
            const int k = ks * 8 + (lane & 3);
            uint32_t a[2][4], b[8][2];
            #pragma unroll
            for (int mi = 0; mi < 2; mi++) {
                int r = warp_m * 32 + mi * 16 + (lane >> 2);
                a[mi][0] = As_[r * GS_STRIDE + k];
                a[mi][1] = As_[(r + 8) * GS_STRIDE + k];
                a[mi][2] = As_[r * GS_STRIDE + k + 4];
                a[mi][3] = As_[(r + 8) * GS_STRIDE + k + 4];
            }
            #pragma unroll
            for (int ni = 0; ni < 8; ni++) {
                int n = warp_n * 64 + ni * 8 + (lane >> 2);
                b[ni][0] = Bs_[n * GS_STRIDE + k];
                b[ni][1] = Bs_[n * GS_STRIDE + k + 4];
            }
            #pragma unroll
            for (int mi = 0; mi < 2; mi++)
                #pragma unroll
                for (int ni = 0; ni < 8; ni++) {
                    asm volatile(
                        "mma.sync.aligned.m16n8k8.row.col.f32.tf32.tf32.f32 "
                        "{%0,%1,%2,%3}, {%4,%5,%6,%7}, {%8,%9}, {%0,%1,%2,%3};"
                        : "+f"(c[mi][ni][0]), "+f"(c[mi][ni][1]),
                          "+f"(c[mi][ni][2]), "+f"(c[mi][ni][3])
                        : "r"(a[mi][0]), "r"(a[mi][1]), "r"(a[mi][2]), "r"(a[mi][3]),
                          "r"(b[ni][0]), "r"(b[ni][1]));
                }
        }

        // store prefetched tile into the other buffer
        if (kt + 1 < nT) {
            uint32_t* as = (uint32_t*)(Asm + (buf ^ 1) * GS_BUF) + lrow * GS_STRIDE + lseg;
            uint32_t* bs = (uint32_t*)(Bsm + (buf ^ 1) * GS_BUF) + lrow * GS_STRIDE + lseg;
            #pragma unroll
            for (int j = 0; j < 4; j++) {
                uint4 ua = { cvt_tf32(pa[j].x), cvt_tf32(pa[j].y),
                             cvt_tf32(pa[j].z), cvt_tf32(pa[j].w) };
                uint4 ub = { cvt_tf32(pb[j].x), cvt_tf32(pb[j].y),
                             cvt_tf32(pb[j].z), cvt_tf32(pb[j].w) };
                *(uint4*)(as + j * 4) = ua;
                *(uint4*)(bs + j * 4) = ub;
            }
        }
        __syncthreads();
    }

    // epilogue: C fragments + bias
    #pragma unroll
    for (int mi = 0; mi < 2; mi++) {
        const int row = row0 + warp_m * 32 + mi * 16 + (lane >> 2);
        #pragma unroll
        for (int ni = 0; ni < 8; ni++) {
            const int col = col0 + warp_n * 64 + ni * 8 + 2 * (lane & 3);
            float2 v0, v1;
            v0.x = c[mi][ni][0] + bias[col];
            v0.y = c[mi][ni][1] + bias[col + 1];
            v1.x = c[mi][ni][2] + bias[col];
            v1.y = c[mi][ni][3] + bias[col + 1];
            *(float2*)(C + (size_t)row * N + col) = v0;
            *(float2*)(C + (size_t)(row + 8) * N + col) = v1;
        }
    }
}

// ---------------- RoPE + split qkv -> Q,K,V [B,H,T,D] -----------------------
__global__ void rope_kernel()
{
    int idx = blockIdx.x * blockDim.x + threadIdx.x;
    int i = idx & 31;
    int h = (idx >> 5) & (NH - 1);
    int t = (idx >> 9) & (T_ - 1);
    int b = idx >> 20;

    const float* base = g_qkv + (size_t)(b * T_ + t) * (3 * HID);

    float invf = (float)exp((double)i * (-log(10000.0) / 32.0));
    float ang = (float)t * invf;
    float s, c;
    sincosf(ang, &s, &c);

    int col = h * HD + i;
    float q1 = base[col],           q2 = base[col + 32];
    float k1 = base[HID + col],     k2 = base[HID + col + 32];
    float v1 = base[2 * HID + col], v2 = base[2 * HID + col + 32];

    size_t o = (((size_t)b * NH + h) * T_ + t) * HD + i;
    g_Q[o]      = q1 * c - q2 * s;
    g_Q[o + 32] = q1 * s + q2 * c;
    g_K[o]      = k1 * c - k2 * s;
    g_K[o + 32] = k1 * s + k2 * c;
    g_V[o]      = v1;
    g_V[o + 32] = v2;
}

// ---------------- global-token mask + list ----------------------------------
__global__ void ginit_kernel()
{
    if (threadIdx.x < B_) g_gcnt[threadIdx.x] = 0;
}

__global__ void gmask_kernel(const int* __restrict__ ids)
{
    int idx = blockIdx.x * blockDim.x + threadIdx.x;
    if (idx >= B_ * T_) return;
    int id = ids[idx];
    bool g = (id >= 0 && id <= 2);
    g_gmask[idx] = g ? 1 : 0;
    if (g) {
        int b = idx / T_;
        int p = atomicAdd(&g_gcnt[b], 1);
        g_glist[b * T_ + p] = idx - b * T_;
    }
}

// ---------------- flash attention (causal + global columns) -----------------
__global__ __launch_bounds__(128) void attn_kernel()
{
    const int b  = blockIdx.z;
    const int h  = blockIdx.y;
    const int q0 = blockIdx.x * 128;
    const int tid = threadIdx.x;
    const int q = q0 + tid;

    const size_t head_off = ((size_t)b * NH + h) * T_ * HD;
    const float* Qr = g_Q + head_off + (size_t)q * HD;
    const float* Kb = g_K + head_off;
    const float* Vb = g_V + head_off;

    float qreg[HD];
    #pragma unroll
    for (int d = 0; d < HD; d += 4) {
        float4 v = *(const float4*)(Qr + d);
        qreg[d] = v.x; qreg[d + 1] = v.y; qreg[d + 2] = v.z; qreg[d + 3] = v.w;
    }
    float oacc[HD];
    #pragma unroll
    for (int d = 0; d < HD; d++) oacc[d] = 0.f;
    float m = -1e30f, l = 0.f;

    __shared__ float Ks[32][HD];
    __shared__ float Vs[32][HD];
    __shared__ signed char gm[32];

    const int kend = q0 + 128;

    for (int t0 = 0; t0 < kend; t0 += 32) {
        #pragma unroll 4
        for (int i = tid; i < 32 * 16; i += 128) {
            int r = i >> 4, c = (i & 15) << 2;
            *(float4*)&Ks[r][c] = *(const float4*)(Kb + (size_t)(t0 + r) * HD + c);
            *(float4*)&Vs[r][c] = *(const float4*)(Vb + (size_t)(t0 + r) * HD + c);
        }
        if (tid < 32) gm[tid] = g_gmask[b * T_ + t0 + tid];
        __syncthreads();

        #pragma unroll
        for (int ch = 0; ch < 2; ch++) {
            float s[16];
            #pragma unroll
            for (int jj = 0; jj < 16; jj++) {
                const int j = ch * 16 + jj;
                float acc = 0.f;
                #pragma unroll
                for (int d = 0; d < HD; d++)
                    acc = fmaf(qreg[d], Ks[j][d], acc);
                int k = t0 + j;
                bool allow = (k <= q) || (gm[j] != 0);
                s[jj] = allow ? acc * 0.125f : -1e30f;
            }
            float cmax = s[0];
            #pragma unroll
            for (int jj = 1; jj < 16; jj++) cmax = fmaxf(cmax, s[jj]);
            float mnew = fmaxf(m, cmax);
            float alpha = __expf(m - mnew);
            l *= alpha;
            #pragma unroll
            for (int d = 0; d < HD; d++) oacc[d] *= alpha;
            #pragma unroll
            for (int jj = 0; jj < 16; jj++) {
                const int j = ch * 16 + jj;
                float p = __expf(s[jj] - mnew);
                l += p;
                #pragma unroll
                for (int d = 0; d < HD; d++)
                    oacc[d] = fmaf(p, Vs[j][d], oacc[d]);
            }
            m = mnew;
        }
        __syncthreads();
    }

    const int ng = g_gcnt[b];
    for (int gi = 0; gi < ng; gi++) {
        int k = g_glist[b * T_ + gi];
        if (k < kend) continue;
        const float* Kr = Kb + (size_t)k * HD;
        const float* Vr = Vb + (size_t)k * HD;
        float acc = 0.f;
        #pragma unroll
        for (int d = 0; d < HD; d++) acc = fmaf(qreg[d], __ldg(Kr + d), acc);
        float sv = acc * 0.125f;
        float mnew = fmaxf(m, sv);
        float alpha = __expf(m - mnew);
        float p = __expf(sv - mnew);
        l = l * alpha + p;
        #pragma unroll
        for (int d = 0; d < HD; d++)
            oacc[d] = oacc[d] * alpha + p * __ldg(Vr + d);
        m = mnew;
    }

    float inv = 1.f / l;
    float* Or = g_att + ((size_t)(b * T_ + q)) * HID + h * HD;
    #pragma unroll
    for (int d = 0; d < HD; d += 4) {
        float4 v;
        v.x = oacc[d + 0] * inv; v.y = oacc[d + 1] * inv;
        v.z = oacc[d + 2] * inv; v.w = oacc[d + 3] * inv;
        *(float4*)(Or + d) = v;
    }
}

// ---------------- launch -----------------------------------------------------
extern "C" void kernel_launch(void* const* d_in, const int* in_sizes, int n_in,
                              void* d_out, int out_size)
{
    (void)in_sizes; (void)n_in; (void)out_size;
    const float* x      = (const float*)d_in[0];
    const int*   ids    = (const int*)d_in[1];
    const float* qkv_w  = (const float*)d_in[2];
    const float* qkv_b  = (const float*)d_in[3];
    const float* out_w  = (const float*)d_in[4];
    const float* out_b  = (const float*)d_in[5];
    float*       out    = (float*)d_out;

    float *p_qkv = nullptr, *p_att = nullptr;
    cudaGetSymbolAddress((void**)&p_qkv, g_qkv);
    cudaGetSymbolAddress((void**)&p_att, g_att);

    cudaFuncSetAttribute(gemm_tf32_mma,
                         cudaFuncAttributeMaxDynamicSharedMemorySize, GS_TOTAL);

    // 1. qkv = x @ qkv_w^T + qkv_b   [4096, 3072]
    gemm_tf32_mma<<<dim3(3 * HID / 128, (B_ * T_) / 128), 256, GS_TOTAL>>>(
        x, qkv_w, qkv_b, p_qkv, 3 * HID, HID);

    // 2. RoPE + split to [B,H,T,D]
    rope_kernel<<<(B_ * T_ * NH * 32) / 256, 256>>>();

    // 3. global-token mask + list
    ginit_kernel<<<1, 32>>>();
    gmask_kernel<<<(B_ * T_ + 255) / 256, 256>>>(ids);

    // 4. attention -> g_att [B*T, 1024]
    attn_kernel<<<dim3(T_ / 128, NH, B_), 128>>>();

    // 5. out = att @ out_w^T + out_b  [4096, 1024]
    gemm_tf32_mma<<<dim3(HID / 128, (B_ * T_) / 128), 256, GS_TOTAL>>>(
        p_att, out_w, out_b, out, HID, HID);
}

// round 4
// speedup vs baseline: 2.6394x; 1.9950x over previous
#include <cuda_runtime.h>
#include <math.h>
#include <stdint.h>

#define B_   2
#define T_   2048
#define HID  1024
#define NH   16
#define HD   64

// ---------------- scratch (device globals; no allocations allowed) ----------
__device__ float g_qkv[B_ * T_ * 3 * HID];
__device__ float g_Q[B_ * NH * T_ * HD];
__device__ float g_K[B_ * NH * T_ * HD];
__device__ float g_V[B_ * NH * T_ * HD];
__device__ float g_att[B_ * T_ * HID];
__device__ signed char g_gmask[B_ * T_];
__device__ int g_gcnt[B_];
__device__ int g_glist[B_ * T_];

__device__ __forceinline__ uint32_t cvt_tf32(float f) {
    uint32_t r;
    asm("cvt.rna.tf32.f32 %0, %1;" : "=r"(r) : "f"(f));
    return r;
}

__device__ __forceinline__ void mma_tf32_16n8k8(
    float* c, uint32_t a0, uint32_t a1, uint32_t a2, uint32_t a3,
    uint32_t b0, uint32_t b1)
{
    asm volatile(
        "mma.sync.aligned.m16n8k8.row.col.f32.tf32.tf32.f32 "
        "{%0,%1,%2,%3}, {%4,%5,%6,%7}, {%8,%9}, {%0,%1,%2,%3};"
        : "+f"(c[0]), "+f"(c[1]), "+f"(c[2]), "+f"(c[3])
        : "r"(a0), "r"(a1), "r"(a2), "r"(a3), "r"(b0), "r"(b1));
}

// ---------------- TF32 mma.sync GEMM (unchanged from R3) ---------------------
#define GS_STRIDE 36
#define GS_BUF    (128 * GS_STRIDE)
#define GS_TOTAL  (4 * GS_BUF * 4)

__global__ __launch_bounds__(256) void gemm_tf32_mma(
    const float* __restrict__ A, const float* __restrict__ W,
    const float* __restrict__ bias, float* __restrict__ C,
    int N, int K)
{
    extern __shared__ float sm[];
    float* Asm = sm;
    float* Bsm = sm + 2 * GS_BUF;

    const int tid = threadIdx.x;
    const int lane = tid & 31;
    const int wid = tid >> 5;
    const int warp_m = wid & 3;
    const int warp_n = wid >> 2;
    const int row0 = blockIdx.y * 128;
    const int col0 = blockIdx.x * 128;

    const int lrow = tid >> 1;
    const int lseg = (tid & 1) * 16;

    const float* Ag = A + (size_t)(row0 + lrow) * K + lseg;
    const float* Bg = W + (size_t)(col0 + lrow) * K + lseg;

    float c[2][8][4];
    #pragma unroll
    for (int mi = 0; mi < 2; mi++)
        #pragma unroll
        for (int ni = 0; ni < 8; ni++)
            #pragma unroll
            for (int r = 0; r < 4; r++) c[mi][ni][r] = 0.f;

    float4 pa[4], pb[4];
    const int nT = K / 32;

    #pragma unroll
    for (int j = 0; j < 4; j++) {
        pa[j] = *(const float4*)(Ag + j * 4);
        pb[j] = *(const float4*)(Bg + j * 4);
    }
    {
        uint32_t* as = (uint32_t*)(Asm) + lrow * GS_STRIDE + lseg;
        uint32_t* bs = (uint32_t*)(Bsm) + lrow * GS_STRIDE + lseg;
        #pragma unroll
        for (int j = 0; j < 4; j++) {
            uint4 ua = { cvt_tf32(pa[j].x), cvt_tf32(pa[j].y),
                         cvt_tf32(pa[j].z), cvt_tf32(pa[j].w) };
            uint4 ub = { cvt_tf32(pb[j].x), cvt_tf32(pb[j].y),
                         cvt_tf32(pb[j].z), cvt_tf32(pb[j].w) };
            *(uint4*)(as + j * 4) = ua;
            *(uint4*)(bs + j * 4) = ub;
        }
    }
    __syncthreads();

    for (int kt = 0; kt < nT; kt++) {
        const int buf = kt & 1;
        if (kt + 1 < nT) {
            const float* Ap = Ag + (kt + 1) * 32;
            const float* Bp = Bg + (kt + 1) * 32;
            #pragma unroll
            for (int j = 0; j < 4; j++) {
                pa[j] = *(const float4*)(Ap + j * 4);
                pb[j] = *(const float4*)(Bp + j * 4);
            }
        }

        const uint32_t* As_ = (const uint32_t*)(Asm + buf * GS_BUF);
        const uint32_t* Bs_ = (const uint32_t*)(Bsm + buf * GS_BUF);
        #pragma unroll
        for (int ks = 0; ks < 4; ks++) {
            const int k = ks * 8 + (lane & 3);
            uint32_t a[2][4], b[8][2];
            #pragma unroll
            for (int mi = 0; mi < 2; mi++) {
                int r = warp_m * 32 + mi * 16 + (lane >> 2);
                a[mi][0] = As_[r * GS_STRIDE + k];
                a[mi][1] = As_[(r + 8) * GS_STRIDE + k];
                a[mi][2] = As_[r * GS_STRIDE + k + 4];
                a[mi][3] = As_[(r + 8) * GS_STRIDE + k + 4];
            }
            #pragma unroll
            for (int ni = 0; ni < 8; ni++) {
                int n = warp_n * 64 + ni * 8 + (lane >> 2);
                b[ni][0] = Bs_[n * GS_STRIDE + k];
                b[ni][1] = Bs_[n * GS_STRIDE + k + 4];
            }
            #pragma unroll
            for (int mi = 0; mi < 2; mi++)
                #pragma unroll
                for (int ni = 0; ni < 8; ni++)
                    mma_tf32_16n8k8(c[mi][ni], a[mi][0], a[mi][1], a[mi][2], a[mi][3],
                                    b[ni][0], b[ni][1]);
        }

        if (kt + 1 < nT) {
            uint32_t* as = (uint32_t*)(Asm + (buf ^ 1) * GS_BUF) + lrow * GS_STRIDE + lseg;
            uint32_t* bs = (uint32_t*)(Bsm + (buf ^ 1) * GS_BUF) + lrow * GS_STRIDE + lseg;
            #pragma unroll
            for (int j = 0; j < 4; j++) {
                uint4 ua = { cvt_tf32(pa[j].x), cvt_tf32(pa[j].y),
                             cvt_tf32(pa[j].z), cvt_tf32(pa[j].w) };
                uint4 ub = { cvt_tf32(pb[j].x), cvt_tf32(pb[j].y),
                             cvt_tf32(pb[j].z), cvt_tf32(pb[j].w) };
                *(uint4*)(as + j * 4) = ua;
                *(uint4*)(bs + j * 4) = ub;
            }
        }
        __syncthreads();
    }

    #pragma unroll
    for (int mi = 0; mi < 2; mi++) {
        const int row = row0 + warp_m * 32 + mi * 16 + (lane >> 2);
        #pragma unroll
        for (int ni = 0; ni < 8; ni++) {
            const int col = col0 + warp_n * 64 + ni * 8 + 2 * (lane & 3);
            float2 v0, v1;
            v0.x = c[mi][ni][0] + bias[col];
            v0.y = c[mi][ni][1] + bias[col + 1];
            v1.x = c[mi][ni][2] + bias[col];
            v1.y = c[mi][ni][3] + bias[col + 1];
            *(float2*)(C + (size_t)row * N + col) = v0;
            *(float2*)(C + (size_t)(row + 8) * N + col) = v1;
        }
    }
}

// ---------------- RoPE + split qkv -> Q,K,V [B,H,T,D] -----------------------
__global__ void rope_kernel()
{
    int idx = blockIdx.x * blockDim.x + threadIdx.x;
    int i = idx & 31;
    int h = (idx >> 5) & (NH - 1);
    int t = (idx >> 9) & (T_ - 1);
    int b = idx >> 20;

    const float* base = g_qkv + (size_t)(b * T_ + t) * (3 * HID);

    float invf = (float)exp((double)i * (-log(10000.0) / 32.0));
    float ang = (float)t * invf;
    float s, c;
    sincosf(ang, &s, &c);

    int col = h * HD + i;
    float q1 = base[col],           q2 = base[col + 32];
    float k1 = base[HID + col],     k2 = base[HID + col + 32];
    float v1 = base[2 * HID + col], v2 = base[2 * HID + col + 32];

    size_t o = (((size_t)b * NH + h) * T_ + t) * HD + i;
    g_Q[o]      = q1 * c - q2 * s;
    g_Q[o + 32] = q1 * s + q2 * c;
    g_K[o]      = k1 * c - k2 * s;
    g_K[o + 32] = k1 * s + k2 * c;
    g_V[o]      = v1;
    g_V[o + 32] = v2;
}

// ---------------- global-token mask + list ----------------------------------
__global__ void ginit_kernel()
{
    if (threadIdx.x < B_) g_gcnt[threadIdx.x] = 0;
}

__global__ void gmask_kernel(const int* __restrict__ ids)
{
    int idx = blockIdx.x * blockDim.x + threadIdx.x;
    if (idx >= B_ * T_) return;
    int id = ids[idx];
    bool g = (id >= 0 && id <= 2);
    g_gmask[idx] = g ? 1 : 0;
    if (g) {
        int b = idx / T_;
        int p = atomicAdd(&g_gcnt[b], 1);
        g_glist[b * T_ + p] = idx - b * T_;
    }
}

// ---------------- flash attention with tf32 mma ------------------------------
// Block = 128 q rows of one (b,h). 256 threads = 8 warps, 16 rows/warp.
// Key tiles of 64. S and O in m16n8k8 fragments; P staged in SMEM (tf32).
// SMEM strides: Q/K/P = 68 (QK b-frag + a-frag conflict-free),
//               V = 72 (PV b-frag conflict-free: bank = 8*tig+g distinct).
#define AQ_STR 68
#define AK_STR 68
#define AV_STR 72
#define AP_STR 68
#define AQ_OFF 0
#define AK_OFF (128 * AQ_STR)                 // 8704
#define AV_OFF (AK_OFF + 64 * AK_STR)         // 13056
#define AP_OFF (AV_OFF + 64 * AV_STR)         // 17664
#define A_SMEM_U32 (AP_OFF + 128 * AP_STR)    // 26368
#define A_SMEM_BYTES (A_SMEM_U32 * 4)         // 105472

__global__ __launch_bounds__(256) void attn_mma_kernel()
{
    extern __shared__ uint32_t smu[];
    __shared__ unsigned char gms[64];

    const int b   = blockIdx.z;
    const int h   = blockIdx.y;
    const int q0  = blockIdx.x * 128;
    const int tid = threadIdx.x;
    const int lane = tid & 31;
    const int wid  = tid >> 5;                 // 0..7
    const int g    = lane >> 2;                // 0..7
    const int tig  = lane & 3;                 // 0..3

    const size_t head_off = ((size_t)b * NH + h) * T_ * HD;
    const float* Qg = g_Q + head_off;
    const float* Kg = g_K + head_off;
    const float* Vg = g_V + head_off;

    // fill Q tile (scaled by 1/8, tf32)
    #pragma unroll
    for (int it = 0; it < 8; it++) {
        int i = tid + it * 256;                 // 0..2047
        int r = i >> 4, seg = (i & 15) << 2;
        float4 v = *(const float4*)(Qg + (size_t)(q0 + r) * HD + seg);
        uint32_t* d = smu + AQ_OFF + r * AQ_STR + seg;
        d[0] = cvt_tf32(v.x * 0.125f); d[1] = cvt_tf32(v.y * 0.125f);
        d[2] = cvt_tf32(v.z * 0.125f); d[3] = cvt_tf32(v.w * 0.125f);
    }

    float o[8][4];
    #pragma unroll
    for (int nt = 0; nt < 8; nt++)
        #pragma unroll
        for (int r = 0; r < 4; r++) o[nt][r] = 0.f;
    float m0 = -1e30f, m1 = -1e30f, l0 = 0.f, l1 = 0.f;

    const int row_l0 = wid * 16 + g;           // local row
    const int row_q0 = q0 + row_l0;            // global q index
    const int row_q1 = row_q0 + 8;
    const int qmin   = q0 + wid * 16;
    const int kend   = q0 + 128;

    for (int t0 = 0; t0 < kend; t0 += 64) {
        // fill K/V tiles (tf32)
        #pragma unroll
        for (int it = 0; it < 4; it++) {
            int i = tid + it * 256;             // 0..1023
            int r = i >> 4, seg = (i & 15) << 2;
            float4 kv = *(const float4*)(Kg + (size_t)(t0 + r) * HD + seg);
            float4 vv = *(const float4*)(Vg + (size_t)(t0 + r) * HD + seg);
            uint32_t* dk = smu + AK_OFF + r * AK_STR + seg;
            uint32_t* dv = smu + AV_OFF + r * AV_STR + seg;
            dk[0] = cvt_tf32(kv.x); dk[1] = cvt_tf32(kv.y);
            dk[2] = cvt_tf32(kv.z); dk[3] = cvt_tf32(kv.w);
            dv[0] = cvt_tf32(vv.x); dv[1] = cvt_tf32(vv.y);
            dv[2] = cvt_tf32(vv.z); dv[3] = cvt_tf32(vv.w);
        }
        if (tid < 64) gms[tid] = (unsigned char)g_gmask[b * T_ + t0 + tid];
        __syncthreads();

        // ---- QK^T: S[16][64] per warp ----
        float s[8][4];
        #pragma unroll
        for (int nt = 0; nt < 8; nt++)
            #pragma unroll
            for (int r = 0; r < 4; r++) s[nt][r] = 0.f;

        #pragma unroll
        for (int ks = 0; ks < 8; ks++) {
            const int kk = ks * 8 + tig;
            uint32_t a0 = smu[AQ_OFF + (row_l0)     * AQ_STR + kk];
            uint32_t a1 = smu[AQ_OFF + (row_l0 + 8) * AQ_STR + kk];
            uint32_t a2 = smu[AQ_OFF + (row_l0)     * AQ_STR + kk + 4];
            uint32_t a3 = smu[AQ_OFF + (row_l0 + 8) * AQ_STR + kk + 4];
            uint32_t bb[8][2];
            #pragma unroll
            for (int nt = 0; nt < 8; nt++) {
                bb[nt][0] = smu[AK_OFF + (nt * 8 + g) * AK_STR + kk];
                bb[nt][1] = smu[AK_OFF + (nt * 8 + g) * AK_STR + kk + 4];
            }
            #pragma unroll
            for (int nt = 0; nt < 8; nt++)
                mma_tf32_16n8k8(s[nt], a0, a1, a2, a3, bb[nt][0], bb[nt][1]);
        }

        // ---- mask + online softmax ----
        const bool need_mask = (t0 + 63 > qmin);
        float rm0 = -1e30f, rm1 = -1e30f;
        #pragma unroll
        for (int nt = 0; nt < 8; nt++) {
            if (need_mask) {
                int kcol = t0 + nt * 8 + 2 * tig;
                bool gm0 = gms[nt * 8 + 2 * tig] != 0;
                bool gm1 = gms[nt * 8 + 2 * tig + 1] != 0;
                if (!(kcol     <= row_q0 || gm0)) s[nt][0] = -1e30f;
                if (!(kcol + 1 <= row_q0 || gm1)) s[nt][1] = -1e30f;
                if (!(kcol     <= row_q1 || gm0)) s[nt][2] = -1e30f;
                if (!(kcol + 1 <= row_q1 || gm1)) s[nt][3] = -1e30f;
            }
            rm0 = fmaxf(rm0, fmaxf(s[nt][0], s[nt][1]));
            rm1 = fmaxf(rm1, fmaxf(s[nt][2], s[nt][3]));
        }
        rm0 = fmaxf(rm0, __shfl_xor_sync(0xffffffffu, rm0, 1));
        rm0 = fmaxf(rm0, __shfl_xor_sync(0xffffffffu, rm0, 2));
        rm1 = fmaxf(rm1, __shfl_xor_sync(0xffffffffu, rm1, 1));
        rm1 = fmaxf(rm1, __shfl_xor_sync(0xffffffffu, rm1, 2));

        float mn0 = fmaxf(m0, rm0), mn1 = fmaxf(m1, rm1);
        float al0 = __expf(m0 - mn0), al1 = __expf(m1 - mn1);
        l0 *= al0; l1 *= al1;
        #pragma unroll
        for (int nt = 0; nt < 8; nt++) {
            o[nt][0] *= al0; o[nt][1] *= al0;
            o[nt][2] *= al1; o[nt][3] *= al1;
        }
        uint32_t* P0 = smu + AP_OFF + (row_l0)     * AP_STR;
        uint32_t* P1 = smu + AP_OFF + (row_l0 + 8) * AP_STR;
        #pragma unroll
        for (int nt = 0; nt < 8; nt++) {
            float p0 = __expf(s[nt][0] - mn0), p1 = __expf(s[nt][1] - mn0);
            float p2 = __expf(s[nt][2] - mn1), p3 = __expf(s[nt][3] - mn1);
            l0 += p0 + p1; l1 += p2 + p3;
            int cc = nt * 8 + 2 * tig;
            P0[cc] = cvt_tf32(p0); P0[cc + 1] = cvt_tf32(p1);
            P1[cc] = cvt_tf32(p2); P1[cc + 1] = cvt_tf32(p3);
        }
        m0 = mn0; m1 = mn1;
        __syncthreads();

        // ---- PV: O += P @ V ----
        #pragma unroll
        for (int ks = 0; ks < 8; ks++) {
            const int kk = ks * 8 + tig;
            uint32_t a0 = smu[AP_OFF + (row_l0)     * AP_STR + kk];
            uint32_t a1 = smu[AP_OFF + (row_l0 + 8) * AP_STR + kk];
            uint32_t a2 = smu[AP_OFF + (row_l0)     * AP_STR + kk + 4];
            uint32_t a3 = smu[AP_OFF + (row_l0 + 8) * AP_STR + kk + 4];
            uint32_t bb[8][2];
            #pragma unroll
            for (int nt = 0; nt < 8; nt++) {
                bb[nt][0] = smu[AV_OFF + (ks * 8 + tig)     * AV_STR + nt * 8 + g];
                bb[nt][1] = smu[AV_OFF + (ks * 8 + tig + 4) * AV_STR + nt * 8 + g];
            }
            #pragma unroll
            for (int nt = 0; nt < 8; nt++)
                mma_tf32_16n8k8(o[nt], a0, a1, a2, a3, bb[nt][0], bb[nt][1]);
        }
        __syncthreads();
    }

    // full row sums (across the 4 lanes of the group)
    l0 += __shfl_xor_sync(0xffffffffu, l0, 1);
    l0 += __shfl_xor_sync(0xffffffffu, l0, 2);
    l1 += __shfl_xor_sync(0xffffffffu, l1, 1);
    l1 += __shfl_xor_sync(0xffffffffu, l1, 2);

    // tail: rare global tokens beyond kend (fp32 scalar)
    const int ng = g_gcnt[b];
    for (int gi = 0; gi < ng; gi++) {
        int k = g_glist[b * T_ + gi];
        if (k < kend) continue;
        const float* Kr = Kg + (size_t)k * HD;
        const float* Vr = Vg + (size_t)k * HD;
        const float* q0p = Qg + (size_t)row_q0 * HD;
        const float* q1p = Qg + (size_t)row_q1 * HD;
        float s0 = 0.f, s1 = 0.f;
        #pragma unroll
        for (int d = 0; d < HD; d++) {
            float kv = __ldg(Kr + d);
            s0 = fmaf(__ldg(q0p + d), kv, s0);
            s1 = fmaf(__ldg(q1p + d), kv, s1);
        }
        s0 *= 0.125f; s1 *= 0.125f;
        float mn0 = fmaxf(m0, s0), mn1 = fmaxf(m1, s1);
        float al0 = __expf(m0 - mn0), al1 = __expf(m1 - mn1);
        float p0 = __expf(s0 - mn0), p1 = __expf(s1 - mn1);
        l0 = l0 * al0 + p0; l1 = l1 * al1 + p1;
        m0 = mn0; m1 = mn1;
        #pragma unroll
        for (int nt = 0; nt < 8; nt++) {
            int cc = nt * 8 + 2 * tig;
            float v0 = __ldg(Vr + cc), v1 = __ldg(Vr + cc + 1);
            o[nt][0] = o[nt][0] * al0 + p0 * v0;
            o[nt][1] = o[nt][1] * al0 + p0 * v1;
            o[nt][2] = o[nt][2] * al1 + p1 * v0;
            o[nt][3] = o[nt][3] * al1 + p1 * v1;
        }
    }

    // write output
    float i0 = 1.f / l0, i1 = 1.f / l1;
    float* O0 = g_att + ((size_t)(b * T_ + row_q0)) * HID + h * HD;
    float* O1 = g_att + ((size_t)(b * T_ + row_q1)) * HID + h * HD;
    #pragma unroll
    for (int nt = 0; nt < 8; nt++) {
        int cc = nt * 8 + 2 * tig;
        float2 v0 = { o[nt][0] * i0, o[nt][1] * i0 };
        float2 v1 = { o[nt][2] * i1, o[nt][3] * i1 };
        *(float2*)(O0 + cc) = v0;
        *(float2*)(O1 + cc) = v1;
    }
}

// ---------------- launch -----------------------------------------------------
extern "C" void kernel_launch(void* const* d_in, const int* in_sizes, int n_in,
                              void* d_out, int out_size)
{
    (void)in_sizes; (void)n_in; (void)out_size;
    const float* x      = (const float*)d_in[0];
    const int*   ids    = (const int*)d_in[1];
    const float* qkv_w  = (const float*)d_in[2];
    const float* qkv_b  = (const float*)d_in[3];
    const float* out_w  = (const float*)d_in[4];
    const float* out_b  = (const float*)d_in[5];
    float*       out    = (float*)d_out;

    float *p_qkv = nullptr, *p_att = nullptr;
    cudaGetSymbolAddress((void**)&p_qkv, g_qkv);
    cudaGetSymbolAddress((void**)&p_att, g_att);

    cudaFuncSetAttribute(gemm_tf32_mma,
                         cudaFuncAttributeMaxDynamicSharedMemorySize, GS_TOTAL);
    cudaFuncSetAttribute(attn_mma_kernel,
                         cudaFuncAttributeMaxDynamicSharedMemorySize, A_SMEM_BYTES);

    // 1. qkv = x @ qkv_w^T + qkv_b
    gemm_tf32_mma<<<dim3(3 * HID / 128, (B_ * T_) / 128), 256, GS_TOTAL>>>(
        x, qkv_w, qkv_b, p_qkv, 3 * HID, HID);

    // 2. RoPE + split
    rope_kernel<<<(B_ * T_ * NH * 32) / 256, 256>>>();

    // 3. global-token mask
    ginit_kernel<<<1, 32>>>();
    gmask_kernel<<<(B_ * T_ + 255) / 256, 256>>>(ids);

    // 4. attention (tf32 mma flash attention)
    attn_mma_kernel<<<dim3(T_ / 128, NH, B_), 256, A_SMEM_BYTES>>>();

    // 5. out = att @ out_w^T + out_b
    gemm_tf32_mma<<<dim3(HID / 128, (B_ * T_) / 128), 256, GS_TOTAL>>>(
        p_att, out_w, out_b, out, HID, HID);
}

// round 5
// speedup vs baseline: 3.5892x; 1.3599x over previous
#include <cuda_runtime.h>
#include <math.h>
#include <stdint.h>

#define B_   2
#define T_   2048
#define HID  1024
#define NH   16
#define HD   64

// ---------------- scratch (device globals; no allocations allowed) ----------
__device__ float g_Q[B_ * NH * T_ * HD];
__device__ float g_K[B_ * NH * T_ * HD];
__device__ float g_V[B_ * NH * T_ * HD];
__device__ float g_att[B_ * T_ * HID];
__device__ float2 g_ctab[T_ * 32];            // cos/sin table [t][d]
__device__ signed char g_gmask[B_ * T_];
__device__ int g_gcnt[B_];
__device__ int g_glist[B_ * T_];

__device__ __forceinline__ uint32_t cvt_tf32(float f) {
    uint32_t r;
    asm("cvt.rna.tf32.f32 %0, %1;" : "=r"(r) : "f"(f));
    return r;
}

__device__ __forceinline__ void mma_tf32_16n8k8(
    float* c, uint32_t a0, uint32_t a1, uint32_t a2, uint32_t a3,
    uint32_t b0, uint32_t b1)
{
    asm volatile(
        "mma.sync.aligned.m16n8k8.row.col.f32.tf32.tf32.f32 "
        "{%0,%1,%2,%3}, {%4,%5,%6,%7}, {%8,%9}, {%0,%1,%2,%3};"
        : "+f"(c[0]), "+f"(c[1]), "+f"(c[2]), "+f"(c[3])
        : "r"(a0), "r"(a1), "r"(a2), "r"(a3), "r"(b0), "r"(b1));
}

// ---------------- cos/sin table + gcnt init ----------------------------------
__global__ void costab_kernel()
{
    int id = blockIdx.x * blockDim.x + threadIdx.x;   // 65536
    int t = id >> 5, j = id & 31;
    float invf = (float)exp((double)j * (-log(10000.0) / 32.0));
    float ang = (float)t * invf;
    float s, c;
    sincosf(ang, &s, &c);
    g_ctab[id] = make_float2(c, s);
}

__global__ void ginit_kernel()
{
    if (threadIdx.x < B_) g_gcnt[threadIdx.x] = 0;
}

__global__ void gmask_kernel(const int* __restrict__ ids)
{
    int idx = blockIdx.x * blockDim.x + threadIdx.x;
    if (idx >= B_ * T_) return;
    int id = ids[idx];
    bool g = (id >= 0 && id <= 2);
    g_gmask[idx] = g ? 1 : 0;
    if (g) {
        int b = idx / T_;
        int p = atomicAdd(&g_gcnt[b], 1);
        g_glist[b * T_ + p] = idx - b * T_;
    }
}

// ---------------- TF32 mma.sync GEMM -----------------------------------------
// MODE 0: C = A @ W^T + bias (row-major C).
// MODE 1: fused qkv epilogue: split into Q/K/V [B,H,T,D], RoPE applied to Q,K.
#define GS_STRIDE 36
#define GS_BUF    (128 * GS_STRIDE)
#define GS_TOTAL  (4 * GS_BUF * 4)

template<int MODE>
__global__ __launch_bounds__(256) void gemm_tf32_mma(
    const float* __restrict__ A, const float* __restrict__ W,
    const float* __restrict__ bias, float* __restrict__ C,
    int N, int K)
{
    extern __shared__ float sm[];
    float* Asm = sm;
    float* Bsm = sm + 2 * GS_BUF;

    const int tid = threadIdx.x;
    const int lane = tid & 31;
    const int wid = tid >> 5;
    const int warp_m = wid & 3;
    const int warp_n = wid >> 2;
    const int row0 = blockIdx.y * 128;
    const int col0 = blockIdx.x * 128;

    const int lrow = tid >> 1;
    const int lseg = (tid & 1) * 16;

    const float* Ag = A + (size_t)(row0 + lrow) * K + lseg;
    const float* Bg = W + (size_t)(col0 + lrow) * K + lseg;

    float c[2][8][4];
    #pragma unroll
    for (int mi = 0; mi < 2; mi++)
        #pragma unroll
        for (int ni = 0; ni < 8; ni++)
            #pragma unroll
            for (int r = 0; r < 4; r++) c[mi][ni][r] = 0.f;

    float4 pa[4], pb[4];
    const int nT = K / 32;

    #pragma unroll
    for (int j = 0; j < 4; j++) {
        pa[j] = *(const float4*)(Ag + j * 4);
        pb[j] = *(const float4*)(Bg + j * 4);
    }
    {
        uint32_t* as = (uint32_t*)(Asm) + lrow * GS_STRIDE + lseg;
        uint32_t* bs = (uint32_t*)(Bsm) + lrow * GS_STRIDE + lseg;
        #pragma unroll
        for (int j = 0; j < 4; j++) {
            uint4 ua = { cvt_tf32(pa[j].x), cvt_tf32(pa[j].y),
                         cvt_tf32(pa[j].z), cvt_tf32(pa[j].w) };
            uint4 ub = { cvt_tf32(pb[j].x), cvt_tf32(pb[j].y),
                         cvt_tf32(pb[j].z), cvt_tf32(pb[j].w) };
            *(uint4*)(as + j * 4) = ua;
            *(uint4*)(bs + j * 4) = ub;
        }
    }
    __syncthreads();

    for (int kt = 0; kt < nT; kt++) {
        const int buf = kt & 1;
        if (kt + 1 < nT) {
            const float* Ap = Ag + (kt + 1) * 32;
            const float* Bp = Bg + (kt + 1) * 32;
            #pragma unroll
            for (int j = 0; j < 4; j++) {
                pa[j] = *(const float4*)(Ap + j * 4);
                pb[j] = *(const float4*)(Bp + j * 4);
            }
        }

        const uint32_t* As_ = (const uint32_t*)(Asm + buf * GS_BUF);
        const uint32_t* Bs_ = (const uint32_t*)(Bsm + buf * GS_BUF);
        #pragma unroll
        for (int ks = 0; ks < 4; ks++) {
            const int k = ks * 8 + (lane & 3);
            uint32_t a[2][4], b[8][2];
            #pragma unroll
            for (int mi = 0; mi < 2; mi++) {
                int r = warp_m * 32 + mi * 16 + (lane >> 2);
                a[mi][0] = As_[r * GS_STRIDE + k];
                a[mi][1] = As_[(r + 8) * GS_STRIDE + k];
                a[mi][2] = As_[r * GS_STRIDE + k + 4];
                a[mi][3] = As_[(r + 8) * GS_STRIDE + k + 4];
            }
            #pragma unroll
            for (int ni = 0; ni < 8; ni++) {
                int n = warp_n * 64 + ni * 8 + (lane >> 2);
                b[ni][0] = Bs_[n * GS_STRIDE + k];
                b[ni][1] = Bs_[n * GS_STRIDE + k + 4];
            }
            #pragma unroll
            for (int mi = 0; mi < 2; mi++)
                #pragma unroll
                for (int ni = 0; ni < 8; ni++)
                    mma_tf32_16n8k8(c[mi][ni], a[mi][0], a[mi][1], a[mi][2], a[mi][3],
                                    b[ni][0], b[ni][1]);
        }

        if (kt + 1 < nT) {
            uint32_t* as = (uint32_t*)(Asm + (buf ^ 1) * GS_BUF) + lrow * GS_STRIDE + lseg;
            uint32_t* bs = (uint32_t*)(Bsm + (buf ^ 1) * GS_BUF) + lrow * GS_STRIDE + lseg;
            #pragma unroll
            for (int j = 0; j < 4; j++) {
                uint4 ua = { cvt_tf32(pa[j].x), cvt_tf32(pa[j].y),
                             cvt_tf32(pa[j].z), cvt_tf32(pa[j].w) };
                uint4 ub = { cvt_tf32(pb[j].x), cvt_tf32(pb[j].y),
                             cvt_tf32(pb[j].z), cvt_tf32(pb[j].w) };
                *(uint4*)(as + j * 4) = ua;
                *(uint4*)(bs + j * 4) = ub;
            }
        }
        __syncthreads();
    }

    if (MODE == 0) {
        #pragma unroll
        for (int mi = 0; mi < 2; mi++) {
            const int row = row0 + warp_m * 32 + mi * 16 + (lane >> 2);
            #pragma unroll
            for (int ni = 0; ni < 8; ni++) {
                const int col = col0 + warp_n * 64 + ni * 8 + 2 * (lane & 3);
                float2 v0, v1;
                v0.x = c[mi][ni][0] + bias[col];
                v0.y = c[mi][ni][1] + bias[col + 1];
                v1.x = c[mi][ni][2] + bias[col];
                v1.y = c[mi][ni][3] + bias[col + 1];
                *(float2*)(C + (size_t)row * N + col) = v0;
                *(float2*)(C + (size_t)(row + 8) * N + col) = v1;
            }
        }
    } else {
        // fused qkv epilogue: blockIdx.x 0-7 => Q, 8-15 => K, 16-23 => V
        const int sec  = blockIdx.x >> 3;
        const int colw = (blockIdx.x & 7) * 128 + warp_n * 64;  // head-aligned
        #pragma unroll
        for (int mi = 0; mi < 2; mi++) {
            const int row = row0 + warp_m * 32 + mi * 16 + (lane >> 2);
            const int bb = row >> 11, tt = row & (T_ - 1);
            if (sec == 2) {
                #pragma unroll
                for (int ni = 0; ni < 8; ni++) {
                    const int col = colw + ni * 8 + 2 * (lane & 3);
                    const int hh = col >> 6, dd = col & 63;
                    const float b0 = bias[2 * HID + col];
                    const float b1 = bias[2 * HID + col + 1];
                    float* dst = g_V + (((size_t)(bb * NH + hh)) * T_ + tt) * HD + dd;
                    float2 v0 = { c[mi][ni][0] + b0, c[mi][ni][1] + b1 };
                    float2 v1 = { c[mi][ni][2] + b0, c[mi][ni][3] + b1 };
                    *(float2*)dst = v0;
                    *(float2*)(dst + 8 * HD) = v1;
                }
            } else {
                float* dstb = sec ? g_K : g_Q;
                const float* bi = bias + sec * HID;
                #pragma unroll
                for (int ni = 0; ni < 4; ni++) {
                    const int col = colw + ni * 8 + 2 * (lane & 3);
                    const int hh = col >> 6, dd = col & 63;   // dd in [0,30]
                    float x1a = c[mi][ni][0]     + bi[col];
                    float x1b = c[mi][ni][1]     + bi[col + 1];
                    float x2a = c[mi][ni + 4][0] + bi[col + 32];
                    float x2b = c[mi][ni + 4][1] + bi[col + 33];
                    float y1a = c[mi][ni][2]     + bi[col];
                    float y1b = c[mi][ni][3]     + bi[col + 1];
                    float y2a = c[mi][ni + 4][2] + bi[col + 32];
                    float y2b = c[mi][ni + 4][3] + bi[col + 33];
                    float2 cs0 = g_ctab[tt * 32 + dd];
                    float2 cs1 = g_ctab[tt * 32 + dd + 1];
                    float2 ds0 = g_ctab[(tt + 8) * 32 + dd];
                    float2 ds1 = g_ctab[(tt + 8) * 32 + dd + 1];
                    float* dst = dstb + (((size_t)(bb * NH + hh)) * T_ + tt) * HD + dd;
                    float2 r0 = { x1a * cs0.x - x2a * cs0.y, x1b * cs1.x - x2b * cs1.y };
                    float2 r1 = { x1a * cs0.y + x2a * cs0.x, x1b * cs1.y + x2b * cs1.x };
                    float2 r2 = { y1a * ds0.x - y2a * ds0.y, y1b * ds1.x - y2b * ds1.y };
                    float2 r3 = { y1a * ds0.y + y2a * ds0.x, y1b * ds1.y + y2b * ds1.x };
                    *(float2*)dst = r0;
                    *(float2*)(dst + 32) = r1;
                    *(float2*)(dst + 8 * HD) = r2;
                    *(float2*)(dst + 8 * HD + 32) = r3;
                }
            }
        }
    }
}

// ---------------- flash attention with tf32 mma, pipelined K/V ---------------
// Block = 128 q rows of one (b,h); 8 warps, 16 rows/warp; key tiles of 64.
// Double-buffered K/V in SMEM + register prefetch; 1 barrier per tile.
#define AQ_STR 68
#define AK_STR 68
#define AV_STR 72
#define AP_STR 68
#define AQ_OFF 0
#define AK_OFF (128 * AQ_STR)                   // 8704
#define AK_BUF (64 * AK_STR)                    // 4352
#define AV_OFF (AK_OFF + 2 * AK_BUF)            // 17408
#define AV_BUF (64 * AV_STR)                    // 4608
#define AP_OFF (AV_OFF + 2 * AV_BUF)            // 26624
#define A_SMEM_U32 (AP_OFF + 128 * AP_STR)      // 35328
#define A_SMEM_BYTES (A_SMEM_U32 * 4)           // 141312

__global__ __launch_bounds__(256) void attn_mma_kernel()
{
    extern __shared__ uint32_t smu[];
    __shared__ unsigned char gms[2][64];

    const int b   = blockIdx.z;
    const int h   = blockIdx.y;
    const int q0  = (gridDim.x - 1 - blockIdx.x) * 128;   // longest blocks first
    const int tid = threadIdx.x;
    const int lane = tid & 31;
    const int wid  = tid >> 5;
    const int g    = lane >> 2;
    const int tig  = lane & 3;

    const size_t head_off = ((size_t)b * NH + h) * T_ * HD;
    const float* Qg = g_Q + head_off;
    const float* Kg = g_K + head_off;
    const float* Vg = g_V + head_off;

    // fill Q tile (scaled by 1/8, tf32)
    #pragma unroll
    for (int it = 0; it < 8; it++) {
        int i = tid + it * 256;
        int r = i >> 4, seg = (i & 15) << 2;
        float4 v = *(const float4*)(Qg + (size_t)(q0 + r) * HD + seg);
        uint32_t* d = smu + AQ_OFF + r * AQ_STR + seg;
        d[0] = cvt_tf32(v.x * 0.125f); d[1] = cvt_tf32(v.y * 0.125f);
        d[2] = cvt_tf32(v.z * 0.125f); d[3] = cvt_tf32(v.w * 0.125f);
    }

    float o[8][4];
    #pragma unroll
    for (int nt = 0; nt < 8; nt++)
        #pragma unroll
        for (int r = 0; r < 4; r++) o[nt][r] = 0.f;
    float m0 = -1e30f, m1 = -1e30f, l0 = 0.f, l1 = 0.f;

    const int row_l0 = wid * 16 + g;
    const int row_q0 = q0 + row_l0;
    const int row_q1 = row_q0 + 8;
    const int qmin   = q0 + wid * 16;
    const int kend   = q0 + 128;
    const int pr_row = tid >> 4, pr_seg = (tid & 15) << 2;

    // register prefetch of tile 0
    float4 pk[4], pv[4];
    #pragma unroll
    for (int it = 0; it < 4; it++) {
        int r = pr_row + it * 16;
        pk[it] = *(const float4*)(Kg + (size_t)r * HD + pr_seg);
        pv[it] = *(const float4*)(Vg + (size_t)r * HD + pr_seg);
    }

    for (int t0 = 0; t0 < kend; t0 += 64) {
        const int buf = (t0 >> 6) & 1;
        // store prefetched K/V (tf32) into smem buffer
        #pragma unroll
        for (int it = 0; it < 4; it++) {
            int r = pr_row + it * 16;
            uint32_t* dk = smu + AK_OFF + buf * AK_BUF + r * AK_STR + pr_seg;
            uint32_t* dv = smu + AV_OFF + buf * AV_BUF + r * AV_STR + pr_seg;
            dk[0] = cvt_tf32(pk[it].x); dk[1] = cvt_tf32(pk[it].y);
            dk[2] = cvt_tf32(pk[it].z); dk[3] = cvt_tf32(pk[it].w);
            dv[0] = cvt_tf32(pv[it].x); dv[1] = cvt_tf32(pv[it].y);
            dv[2] = cvt_tf32(pv[it].z); dv[3] = cvt_tf32(pv[it].w);
        }
        if (tid < 64) gms[buf][tid] = (unsigned char)g_gmask[b * T_ + t0 + tid];
        __syncthreads();

        // prefetch next tile (overlapped with compute below)
        if (t0 + 64 < kend) {
            #pragma unroll
            for (int it = 0; it < 4; it++) {
                int r = t0 + 64 + pr_row + it * 16;
                pk[it] = *(const float4*)(Kg + (size_t)r * HD + pr_seg);
                pv[it] = *(const float4*)(Vg + (size_t)r * HD + pr_seg);
            }
        }

        const uint32_t* Kb = smu + AK_OFF + buf * AK_BUF;
        const uint32_t* Vb = smu + AV_OFF + buf * AV_BUF;

        // ---- QK^T ----
        float s[8][4];
        #pragma unroll
        for (int nt = 0; nt < 8; nt++)
            #pragma unroll
            for (int r = 0; r < 4; r++) s[nt][r] = 0.f;

        #pragma unroll
        for (int ks = 0; ks < 8; ks++) {
            const int kk = ks * 8 + tig;
            uint32_t a0 = smu[AQ_OFF + (row_l0)     * AQ_STR + kk];
            uint32_t a1 = smu[AQ_OFF + (row_l0 + 8) * AQ_STR + kk];
            uint32_t a2 = smu[AQ_OFF + (row_l0)     * AQ_STR + kk + 4];
            uint32_t a3 = smu[AQ_OFF + (row_l0 + 8) * AQ_STR + kk + 4];
            uint32_t bb[8][2];
            #pragma unroll
            for (int nt = 0; nt < 8; nt++) {
                bb[nt][0] = Kb[(nt * 8 + g) * AK_STR + kk];
                bb[nt][1] = Kb[(nt * 8 + g) * AK_STR + kk + 4];
            }
            #pragma unroll
            for (int nt = 0; nt < 8; nt++)
                mma_tf32_16n8k8(s[nt], a0, a1, a2, a3, bb[nt][0], bb[nt][1]);
        }

        // ---- mask + online softmax ----
        const bool need_mask = (t0 + 63 > qmin);
        float rm0 = -1e30f, rm1 = -1e30f;
        #pragma unroll
        for (int nt = 0; nt < 8; nt++) {
            if (need_mask) {
                int kcol = t0 + nt * 8 + 2 * tig;
                bool gm0 = gms[buf][nt * 8 + 2 * tig] != 0;
                bool gm1 = gms[buf][nt * 8 + 2 * tig + 1] != 0;
                if (!(kcol     <= row_q0 || gm0)) s[nt][0] = -1e30f;
                if (!(kcol + 1 <= row_q0 || gm1)) s[nt][1] = -1e30f;
                if (!(kcol     <= row_q1 || gm0)) s[nt][2] = -1e30f;
                if (!(kcol + 1 <= row_q1 || gm1)) s[nt][3] = -1e30f;
            }
            rm0 = fmaxf(rm0, fmaxf(s[nt][0], s[nt][1]));
            rm1 = fmaxf(rm1, fmaxf(s[nt][2], s[nt][3]));
        }
        rm0 = fmaxf(rm0, __shfl_xor_sync(0xffffffffu, rm0, 1));
        rm0 = fmaxf(rm0, __shfl_xor_sync(0xffffffffu, rm0, 2));
        rm1 = fmaxf(rm1, __shfl_xor_sync(0xffffffffu, rm1, 1));
        rm1 = fmaxf(rm1, __shfl_xor_sync(0xffffffffu, rm1, 2));

        float mn0 = fmaxf(m0, rm0), mn1 = fmaxf(m1, rm1);
        float al0 = __expf(m0 - mn0), al1 = __expf(m1 - mn1);
        l0 *= al0; l1 *= al1;
        #pragma unroll
        for (int nt = 0; nt < 8; nt++) {
            o[nt][0] *= al0; o[nt][1] *= al0;
            o[nt][2] *= al1; o[nt][3] *= al1;
        }
        uint32_t* P0 = smu + AP_OFF + (row_l0)     * AP_STR;
        uint32_t* P1 = smu + AP_OFF + (row_l0 + 8) * AP_STR;
        #pragma unroll
        for (int nt = 0; nt < 8; nt++) {
            float p0 = __expf(s[nt][0] - mn0), p1 = __expf(s[nt][1] - mn0);
            float p2 = __expf(s[nt][2] - mn1), p3 = __expf(s[nt][3] - mn1);
            l0 += p0 + p1; l1 += p2 + p3;
            int cc = nt * 8 + 2 * tig;
            P0[cc] = cvt_tf32(p0); P0[cc + 1] = cvt_tf32(p1);
            P1[cc] = cvt_tf32(p2); P1[cc + 1] = cvt_tf32(p3);
        }
        m0 = mn0; m1 = mn1;
        __syncwarp();          // P is warp-private: warp-level sync suffices

        // ---- PV: O += P @ V ----
        #pragma unroll
        for (int ks = 0; ks < 8; ks++) {
            const int kk = ks * 8 + tig;
            uint32_t a0 = smu[AP_OFF + (row_l0)     * AP_STR + kk];
            uint32_t a1 = smu[AP_OFF + (row_l0 + 8) * AP_STR + kk];
            uint32_t a2 = smu[AP_OFF + (row_l0)     * AP_STR + kk + 4];
            uint32_t a3 = smu[AP_OFF + (row_l0 + 8) * AP_STR + kk + 4];
            uint32_t bb[8][2];
            #pragma unroll
            for (int nt = 0; nt < 8; nt++) {
                bb[nt][0] = Vb[(ks * 8 + tig)     * AV_STR + nt * 8 + g];
                bb[nt][1] = Vb[(ks * 8 + tig + 4) * AV_STR + nt * 8 + g];
            }
            #pragma unroll
            for (int nt = 0; nt < 8; nt++)
                mma_tf32_16n8k8(o[nt], a0, a1, a2, a3, bb[nt][0], bb[nt][1]);
        }
    }

    l0 += __shfl_xor_sync(0xffffffffu, l0, 1);
    l0 += __shfl_xor_sync(0xffffffffu, l0, 2);
    l1 += __shfl_xor_sync(0xffffffffu, l1, 1);
    l1 += __shfl_xor_sync(0xffffffffu, l1, 2);

    // tail: rare global tokens beyond kend
    const int ng = g_gcnt[b];
    for (int gi = 0; gi < ng; gi++) {
        int k = g_glist[b * T_ + gi];
        if (k < kend) continue;
        const float* Kr = Kg + (size_t)k * HD;
        const float* Vr = Vg + (size_t)k * HD;
        const float* q0p = Qg + (size_t)row_q0 * HD;
        const float* q1p = Qg + (size_t)row_q1 * HD;
        float s0 = 0.f, s1 = 0.f;
        #pragma unroll
        for (int d = 0; d < HD; d++) {
            float kv = __ldg(Kr + d);
            s0 = fmaf(__ldg(q0p + d), kv, s0);
            s1 = fmaf(__ldg(q1p + d), kv, s1);
        }
        s0 *= 0.125f; s1 *= 0.125f;
        float mn0 = fmaxf(m0, s0), mn1 = fmaxf(m1, s1);
        float al0 = __expf(m0 - mn0), al1 = __expf(m1 - mn1);
        float p0 = __expf(s0 - mn0), p1 = __expf(s1 - mn1);
        l0 = l0 * al0 + p0; l1 = l1 * al1 + p1;
        m0 = mn0; m1 = mn1;
        #pragma unroll
        for (int nt = 0; nt < 8; nt++) {
            int cc = nt * 8 + 2 * tig;
            float v0 = __ldg(Vr + cc), v1 = __ldg(Vr + cc + 1);
            o[nt][0] = o[nt][0] * al0 + p0 * v0;
            o[nt][1] = o[nt][1] * al0 + p0 * v1;
            o[nt][2] = o[nt][2] * al1 + p1 * v0;
            o[nt][3] = o[nt][3] * al1 + p1 * v1;
        }
    }

    float i0 = 1.f / l0, i1 = 1.f / l1;
    float* O0 = g_att + ((size_t)(b * T_ + row_q0)) * HID + h * HD;
    float* O1 = g_att + ((size_t)(b * T_ + row_q1)) * HID + h * HD;
    #pragma unroll
    for (int nt = 0; nt < 8; nt++) {
        int cc = nt * 8 + 2 * tig;
        float2 v0 = { o[nt][0] * i0, o[nt][1] * i0 };
        float2 v1 = { o[nt][2] * i1, o[nt][3] * i1 };
        *(float2*)(O0 + cc) = v0;
        *(float2*)(O1 + cc) = v1;
    }
}

// ---------------- launch -----------------------------------------------------
extern "C" void kernel_launch(void* const* d_in, const int* in_sizes, int n_in,
                              void* d_out, int out_size)
{
    (void)in_sizes; (void)n_in; (void)out_size;
    const float* x      = (const float*)d_in[0];
    const int*   ids    = (const int*)d_in[1];
    const float* qkv_w  = (const float*)d_in[2];
    const float* qkv_b  = (const float*)d_in[3];
    const float* out_w  = (const float*)d_in[4];
    const float* out_b  = (const float*)d_in[5];
    float*       out    = (float*)d_out;

    float* p_att = nullptr;
    cudaGetSymbolAddress((void**)&p_att, g_att);

    cudaFuncSetAttribute(gemm_tf32_mma<0>,
                         cudaFuncAttributeMaxDynamicSharedMemorySize, GS_TOTAL);
    cudaFuncSetAttribute(gemm_tf32_mma<1>,
                         cudaFuncAttributeMaxDynamicSharedMemorySize, GS_TOTAL);
    cudaFuncSetAttribute(attn_mma_kernel,
                         cudaFuncAttributeMaxDynamicSharedMemorySize, A_SMEM_BYTES);

    // 1. cos/sin table
    costab_kernel<<<T_ * 32 / 256, 256>>>();
    // 2-3. global-token mask
    ginit_kernel<<<1, 32>>>();
    gmask_kernel<<<(B_ * T_ + 255) / 256, 256>>>(ids);
    // 4. fused qkv GEMM + bias + RoPE + split -> g_Q/g_K/g_V
    gemm_tf32_mma<1><<<dim3(3 * HID / 128, (B_ * T_) / 128), 256, GS_TOTAL>>>(
        x, qkv_w, qkv_b, nullptr, 3 * HID, HID);
    // 5. attention
    attn_mma_kernel<<<dim3(T_ / 128, NH, B_), 256, A_SMEM_BYTES>>>();
    // 6. out = att @ out_w^T + out_b
    gemm_tf32_mma<0><<<dim3(HID / 128, (B_ * T_) / 128), 256, GS_TOTAL>>>(
        p_att, out_w, out_b, out, HID, HID);
}